// round 4
// baseline (speedup 1.0000x reference)
#include <cuda_runtime.h>
#include <math.h>

#define NMAX 100000
#define EMAX 1600000

// ---------------- static device scratch (no runtime allocation allowed) ----
__device__ __align__(16) float g_bufA[NMAX * 128];   // 51.2 MB ping
__device__ __align__(16) float g_bufB[NMAX * 128];   // 51.2 MB pong
__device__ int   g_col[EMAX];               // CSR column (src) indices
__device__ int   g_rowptr[NMAX + 1];        // CSR row offsets (by dst)
__device__ int   g_cursor[NMAX];
__device__ int   g_outdeg[NMAX];
__device__ int   g_indeg[NMAX];
__device__ float g_norm_src[NMAX];
__device__ float g_norm_dst[NMAX];
__device__ int   g_bsums[128];              // block sums for scan (<=98 used)
__device__ int   g_is64;                    // edge dtype flag (1 = int64)

// ---------------- edge dtype detection + accessor ---------------------------
// JAX default x64-disabled => edge_index is almost certainly int32, but probe
// the buffer so either layout works.
__global__ void k_detect(const void* ei, int E) {
    if (threadIdx.x == 0 && blockIdx.x == 0) {
        const unsigned long long* p = (const unsigned long long*)ei;
        int cnt = E < 256 ? E : 256;
        int nz = 0;
        for (int i = 0; i < cnt; i++)
            if ((p[i] >> 32) != 0ULL) nz++;
        g_is64 = (nz == 0) ? 1 : 0;   // true int64 indices < N have zero high words
    }
}

__device__ __forceinline__ int edge_at(const void* ei, int E, int which, int e) {
    if (g_is64) return (int)((const long long*)ei)[(size_t)which * E + e];
    return ((const int*)ei)[which * E + e];
}

// ---------------- preprocessing kernels ------------------------------------

__global__ void k_zero(int n) {
    int i = blockIdx.x * blockDim.x + threadIdx.x;
    if (i < n) { g_outdeg[i] = 0; g_indeg[i] = 0; }
}

__global__ void k_degree(const void* __restrict__ ei, int E) {
    int e = blockIdx.x * blockDim.x + threadIdx.x;
    if (e < E) {
        atomicAdd(&g_outdeg[edge_at(ei, E, 0, e)], 1);
        atomicAdd(&g_indeg[edge_at(ei, E, 1, e)], 1);
    }
}

__global__ void k_norm(int n) {
    int i = blockIdx.x * blockDim.x + threadIdx.x;
    if (i < n) {
        int od = g_outdeg[i];
        int id = g_indeg[i];
        g_norm_src[i] = od > 0 ? rsqrtf((float)od) : 0.0f;
        g_norm_dst[i] = id > 0 ? rsqrtf((float)id) : 0.0f;
    }
}

// exclusive scan of g_indeg -> g_rowptr, 3-phase
__global__ void k_scan_local(int n) {
    __shared__ int s[2][1024];
    int t = threadIdx.x;
    int i = blockIdx.x * 1024 + t;
    int v = (i < n) ? g_indeg[i] : 0;
    s[0][t] = v;
    __syncthreads();
    int pin = 0;
    #pragma unroll
    for (int off = 1; off < 1024; off <<= 1) {
        int po = pin ^ 1;
        int val = s[pin][t];
        if (t >= off) val += s[pin][t - off];
        s[po][t] = val;
        __syncthreads();
        pin = po;
    }
    int incl = s[pin][t];
    if (i < n) g_rowptr[i] = incl - v;       // local exclusive
    if (t == 1023) g_bsums[blockIdx.x] = incl;
}

__global__ void k_scan_mid(int nb) {
    if (threadIdx.x == 0) {
        int run = 0;
        for (int b = 0; b < nb; b++) { int t = g_bsums[b]; g_bsums[b] = run; run += t; }
    }
}

__global__ void k_scan_add(int n, int E) {
    int i = blockIdx.x * blockDim.x + threadIdx.x;
    if (i < n) {
        int r = g_rowptr[i] + g_bsums[i >> 10];
        g_rowptr[i] = r;
        g_cursor[i] = r;
    }
    if (i == 0) g_rowptr[n] = E;
}

__global__ void k_fill(const void* __restrict__ ei, int E) {
    int e = blockIdx.x * blockDim.x + threadIdx.x;
    if (e < E) {
        int d = edge_at(ei, E, 1, e);
        int pos = atomicAdd(&g_cursor[d], 1);
        g_col[pos] = edge_at(ei, E, 0, e);
    }
}

// buffer selector resolved on device (no cudaGetSymbolAddress on host)
__device__ __forceinline__ const float* sel_in(int s, const float* ext) {
    return s == 0 ? ext : (s == 1 ? g_bufA : g_bufB);
}
__device__ __forceinline__ float* sel_out(int s, float* ext) {
    return s == 0 ? ext : (s == 1 ? g_bufA : g_bufB);
}

// ---------------- dense: H[i,:] = norm_src[i] * (X[i,:] @ W) ----------------
// X: [n,128] row-major. W: [128,D] row-major. Block tile 64 rows x D cols.
template <int D>
__global__ void __launch_bounds__(256) k_gemm(
    int inSel, const float* __restrict__ Xext,
    const float* __restrict__ W,
    int outSel, float* __restrict__ Hext, int n)
{
    const float* __restrict__ X = sel_in(inSel, Xext);
    float* __restrict__ H = sel_out(outSel, Hext);

    constexpr int TN = D / 32;                 // 4 for D=128, 2 for D=64
    __shared__ __align__(16) float Xs[64 * 32];
    __shared__ __align__(16) float Ws[32 * D];

    int tid = threadIdx.x;
    int cg = tid & 31;
    int rg = tid >> 5;
    int rows0 = blockIdx.x * 64;

    float acc[8][TN];
    #pragma unroll
    for (int m = 0; m < 8; m++)
        #pragma unroll
        for (int c = 0; c < TN; c++) acc[m][c] = 0.0f;

    for (int kc = 0; kc < 128; kc += 32) {
        #pragma unroll
        for (int u = 0; u < 2; u++) {
            int q = tid * 2 + u;               // 0..511
            int row = q >> 3;
            int k4 = q & 7;
            int gr = rows0 + row;
            float4 v = make_float4(0.f, 0.f, 0.f, 0.f);
            if (gr < n) v = *(const float4*)&X[gr * 128 + kc + k4 * 4];
            *(float4*)&Xs[row * 32 + k4 * 4] = v;
        }
        {
            const float4* src = (const float4*)(W + kc * D);
            float4* dst = (float4*)Ws;
            #pragma unroll
            for (int q = tid; q < 32 * D / 4; q += 256) dst[q] = src[q];
        }
        __syncthreads();

        #pragma unroll
        for (int kk = 0; kk < 32; kk++) {
            float a[8];
            #pragma unroll
            for (int m = 0; m < 8; m++) a[m] = Xs[(rg * 8 + m) * 32 + kk];
            float b[TN];
            if (TN == 4) {
                float4 bv = *(const float4*)&Ws[kk * D + cg * 4];
                b[0] = bv.x; b[1] = bv.y; b[2] = bv.z; b[3] = bv.w;
            } else {
                float2 bv = *(const float2*)&Ws[kk * D + cg * 2];
                b[0] = bv.x; b[1] = bv.y;
            }
            #pragma unroll
            for (int m = 0; m < 8; m++)
                #pragma unroll
                for (int c = 0; c < TN; c++)
                    acc[m][c] = fmaf(a[m], b[c], acc[m][c]);
        }
        __syncthreads();
    }

    #pragma unroll
    for (int m = 0; m < 8; m++) {
        int row = rows0 + rg * 8 + m;
        if (row < n) {
            float s = g_norm_src[row];
            if (TN == 4) {
                float4 r;
                r.x = acc[m][0] * s; r.y = acc[m][1] * s;
                r.z = acc[m][2] * s; r.w = acc[m][3] * s;
                *(float4*)&H[row * D + cg * 4] = r;
            } else {
                float2 r;
                r.x = acc[m][0] * s; r.y = acc[m][1] * s;
                *(float2*)&H[row * D + cg * 2] = r;
            }
        }
    }
}

// ---------------- sparse: out[d,:] = act(norm_dst[d]*sum_{s in N(d)} H[s,:] + b)
// One warp per dst node; register accumulators; no float atomics.
template <int D, bool ACT>
__global__ void __launch_bounds__(256) k_agg(
    int inSel, const float* __restrict__ Hext,
    const float* __restrict__ bias,
    int outSel, float* __restrict__ outExt, int n)
{
    const float* __restrict__ H = sel_in(inSel, Hext);
    float* __restrict__ out = sel_out(outSel, outExt);

    int gw = (blockIdx.x * blockDim.x + threadIdx.x) >> 5;
    int lane = threadIdx.x & 31;
    if (gw >= n) return;

    int beg = g_rowptr[gw];
    int end = g_rowptr[gw + 1];
    float4 acc = make_float4(0.f, 0.f, 0.f, 0.f);
    const bool active = lane < D / 4;

    for (int e = beg; e < end; e += 32) {
        int m = end - e; if (m > 32) m = 32;
        int idx = (lane < m) ? g_col[e + lane] : 0;
        for (int j = 0; j < m; j++) {
            int s = __shfl_sync(0xffffffffu, idx, j);
            if (active) {
                float4 v = *(const float4*)&H[s * D + lane * 4];
                acc.x += v.x; acc.y += v.y; acc.z += v.z; acc.w += v.w;
            }
        }
    }

    if (active) {
        float nd = g_norm_dst[gw];
        float4 bb = *(const float4*)&bias[lane * 4];
        float4 r;
        r.x = fmaf(acc.x, nd, bb.x);
        r.y = fmaf(acc.y, nd, bb.y);
        r.z = fmaf(acc.z, nd, bb.z);
        r.w = fmaf(acc.w, nd, bb.w);
        if (ACT) {
            r.x = tanhf(r.x); r.y = tanhf(r.y);
            r.z = tanhf(r.z); r.w = tanhf(r.w);
        }
        *(float4*)&out[gw * D + lane * 4] = r;
    }
}

// ---------------- launch ----------------------------------------------------

extern "C" void kernel_launch(void* const* d_in, const int* in_sizes, int n_in,
                              void* d_out, int out_size)
{
    const float* feat = (const float*)d_in[0];
    const void*  ei   = d_in[1];
    const float* W0 = (const float*)d_in[2]; const float* b0 = (const float*)d_in[3];
    const float* W1 = (const float*)d_in[4]; const float* b1 = (const float*)d_in[5];
    const float* W2 = (const float*)d_in[6]; const float* b2 = (const float*)d_in[7];
    const float* W3 = (const float*)d_in[8]; const float* b3 = (const float*)d_in[9];

    int N = in_sizes[0] / 128;
    int E = in_sizes[1] / 2;

    float* out = (float*)d_out;

    // --- build degrees/norms/CSR ---
    k_detect<<<1, 32>>>(ei, E);
    k_zero  <<<(N + 255) / 256, 256>>>(N);
    k_degree<<<(E + 255) / 256, 256>>>(ei, E);
    k_norm  <<<(N + 255) / 256, 256>>>(N);
    int nb = (N + 1023) / 1024;
    k_scan_local<<<nb, 1024>>>(N);
    k_scan_mid  <<<1, 32>>>(nb);
    k_scan_add  <<<(N + 255) / 256, 256>>>(N, E);
    k_fill      <<<(E + 255) / 256, 256>>>(ei, E);

    int gemmGrid = (N + 63) / 64;
    int aggGrid  = (N * 32 + 255) / 256;     // one warp per node

    // buffer selectors: 0 = external ptr, 1 = g_bufA, 2 = g_bufB
    // layer 0: feat -> B -> A
    k_gemm<128><<<gemmGrid, 256>>>(0, feat, W0, 2, nullptr, N);
    k_agg<128, true><<<aggGrid, 256>>>(2, nullptr, b0, 1, nullptr, N);
    // layer 1: A -> B -> A
    k_gemm<128><<<gemmGrid, 256>>>(1, nullptr, W1, 2, nullptr, N);
    k_agg<128, true><<<aggGrid, 256>>>(2, nullptr, b1, 1, nullptr, N);
    // layer 2: A -> B -> A
    k_gemm<128><<<gemmGrid, 256>>>(1, nullptr, W2, 2, nullptr, N);
    k_agg<128, true><<<aggGrid, 256>>>(2, nullptr, b2, 1, nullptr, N);
    // layer 3: A -> B -> d_out (D=64, no act)
    k_gemm<64><<<gemmGrid, 256>>>(1, nullptr, W3, 2, nullptr, N);
    k_agg<64, false><<<aggGrid, 256>>>(2, nullptr, b3, 0, out, N);
}